// round 9
// baseline (speedup 1.0000x reference)
#include <cuda_runtime.h>
#include <cstdint>

// Problem constants
#define BTOK  65536
#define HID   512
#define DIN   512
#define NEXP  64
#define FOURE 256

// ---------------- scratch (static __device__, no allocation) ----------------
__device__ float g_q1[(size_t)BTOK * HID];   // qe1 output, reused for fused
__device__ float g_q [(size_t)BTOK * HID];   // qe2 output
__device__ float g_t [(size_t)BTOK * FOURE]; // tanh(fused @ Wg1^T)
__device__ float g_l [(size_t)BTOK * NEXP];  // logits

// ---------------- packed f32x2 helpers (sm_103a) ----------------------------
typedef unsigned long long u64;

__device__ __forceinline__ u64 fma2(u64 a, u64 b, u64 c) {
    u64 d;
    asm("fma.rn.f32x2 %0, %1, %2, %3;" : "=l"(d) : "l"(a), "l"(b), "l"(c));
    return d;
}
__device__ __forceinline__ u64 add2(u64 a, u64 b) {
    u64 d;
    asm("add.rn.f32x2 %0, %1, %2;" : "=l"(d) : "l"(a), "l"(b));
    return d;
}
__device__ __forceinline__ u64 dup2(float x) {
    u64 d;
    asm("mov.b64 %0, {%1, %1};" : "=l"(d) : "f"(x));
    return d;
}
__device__ __forceinline__ float2 unpk2(u64 a) {
    float2 r;
    asm("mov.b64 {%0, %1}, %2;" : "=f"(r.x), "=f"(r.y) : "l"(a));
    return r;
}

// ---------------- chunked-Kahan tiled fp32 GEMM: C = act(A @ W^T) -----------
// Conflict-free inner loop:
//   a: 2x LDS.128 (trow quad; 2 distinct addrs/warp -> broadcast)
//   b: 4x LDS.64 from PRE-DUPLICATED pairs Bsd[k][n]=(b,b); lanes tcol=tid&15
//      read stride-8B addresses spanning exactly 128B -> 0 conflicts.
// Thread owns cols {tcol, tcol+16, tcol+32, tcol+48}; rows trow..trow+7.
// Kahan fold every 16 k-steps (chunk structure bit-identical to prior round):
//   y = add2(P, Cn); t = add2(S, y); u = fma2(t,-1,S); Cn = add2(y,u); S = t
// A is logically [M, K]; columns [0,K0) from A0 (row stride K0), columns
// [K0,K) from A1 (row stride K-K0).  W is [N, K] row-major.
#define BM 128
#define BN 64
#define BKK 32

__global__ __launch_bounds__(256, 2) void gemm_bias_act(
    const float* __restrict__ A0, const float* __restrict__ A1, int K0, int K,
    const float* __restrict__ W, const float* __restrict__ bias,
    float* __restrict__ C, int N, int act)
{
    __shared__ __align__(16) float As[BKK][BM];
    __shared__ __align__(16) u64   Bsd[BKK][BN];   // (b, b) duplicated pairs

    const int tid  = threadIdx.x;
    const int m0   = blockIdx.y * BM;
    const int n0   = blockIdx.x * BN;
    const int lr   = tid >> 2;          // 0..63
    const int lc   = (tid & 3) << 2;    // 0,4,8,12 (float4 col within 16)
    const int trow = (tid >> 4) << 3;   // 0..120 step 8
    const int tcol = tid & 15;          // 0..15; cols tcol + 16*j

    const u64 MONE = 0xbf800000bf800000ULL;  // (-1.0f, -1.0f)

    // S[pi][j]: rows (trow+2pi, trow+2pi+1), col n0+tcol+16j.
    u64 S[4][4], Cn[4][4];
#pragma unroll
    for (int pi = 0; pi < 4; pi++)
#pragma unroll
        for (int j = 0; j < 4; j++) { S[pi][j] = 0ull; Cn[pi][j] = 0ull; }

    for (int kt = 0; kt < K; kt += BKK) {
        // ---- load 32-wide k-tile (two 16-col halves) ----
#pragma unroll
        for (int h = 0; h < 2; h++) {
            const int gk = kt + h * 16 + lc;
            float4 av0, av1;
            if (gk < K0) {
                av0 = *(const float4*)(A0 + (size_t)(m0 + lr)      * K0 + gk);
                av1 = *(const float4*)(A0 + (size_t)(m0 + lr + 64) * K0 + gk);
            } else {
                const int K1 = K - K0;
                av0 = *(const float4*)(A1 + (size_t)(m0 + lr)      * K1 + (gk - K0));
                av1 = *(const float4*)(A1 + (size_t)(m0 + lr + 64) * K1 + (gk - K0));
            }
            const float4 bv = *(const float4*)(W + (size_t)(n0 + lr) * K + gk);

            const int kr = h * 16 + lc;
            As[kr + 0][lr] = av0.x; As[kr + 1][lr] = av0.y;
            As[kr + 2][lr] = av0.z; As[kr + 3][lr] = av0.w;
            As[kr + 0][lr + 64] = av1.x; As[kr + 1][lr + 64] = av1.y;
            As[kr + 2][lr + 64] = av1.z; As[kr + 3][lr + 64] = av1.w;

            Bsd[kr + 0][lr] = dup2(bv.x); Bsd[kr + 1][lr] = dup2(bv.y);
            Bsd[kr + 2][lr] = dup2(bv.z); Bsd[kr + 3][lr] = dup2(bv.w);
        }
        __syncthreads();

        // ---- two 16-term chunks, Kahan-folded each (order == prior round) ----
#pragma unroll
        for (int half = 0; half < 2; half++) {
            u64 P[4][4];
#pragma unroll
            for (int pi = 0; pi < 4; pi++)
#pragma unroll
                for (int j = 0; j < 4; j++) P[pi][j] = 0ull;

#pragma unroll
            for (int kk = 0; kk < 16; kk++) {
                const int k = half * 16 + kk;
                const ulonglong2 aq0 = *(const ulonglong2*)&As[k][trow];      // LDS.128
                const ulonglong2 aq1 = *(const ulonglong2*)&As[k][trow + 4];  // LDS.128
                u64 ap[4] = { aq0.x, aq0.y, aq1.x, aq1.y };
                u64 bd[4];
#pragma unroll
                for (int j = 0; j < 4; j++)
                    bd[j] = Bsd[k][tcol + 16 * j];                            // LDS.64 cf
#pragma unroll
                for (int j = 0; j < 4; j++)
#pragma unroll
                    for (int pi = 0; pi < 4; pi++)
                        P[pi][j] = fma2(ap[pi], bd[j], P[pi][j]);
            }

#pragma unroll
            for (int pi = 0; pi < 4; pi++)
#pragma unroll
                for (int j = 0; j < 4; j++) {
                    u64 y = add2(P[pi][j], Cn[pi][j]);
                    u64 t = add2(S[pi][j], y);
                    u64 u = fma2(t, MONE, S[pi][j]);   // s - t (exact)
                    Cn[pi][j] = add2(y, u);            // y - (t - s)
                    S[pi][j]  = t;
                }
        }
        __syncthreads();
    }

    float bb[4];
#pragma unroll
    for (int j = 0; j < 4; j++) bb[j] = bias ? bias[n0 + tcol + 16 * j] : 0.f;

#pragma unroll
    for (int pi = 0; pi < 4; pi++) {
        float* cp0 = C + (size_t)(m0 + trow + 2 * pi)     * N + n0 + tcol;
        float* cp1 = C + (size_t)(m0 + trow + 2 * pi + 1) * N + n0 + tcol;
#pragma unroll
        for (int j = 0; j < 4; j++) {
            float2 v = unpk2(S[pi][j]);
            float xl = v.x + bb[j];
            float xh = v.y + bb[j];
            if (act == 1)      { xl = fmaxf(xl, 0.f); xh = fmaxf(xh, 0.f); }
            else if (act == 2) { xl = tanhf(xl);      xh = tanhf(xh); }
            cp0[16 * j] = xl;
            cp1[16 * j] = xh;
        }
    }
}

// ---------------- epilogue: softmax + top2 + scatter (memory-bound) ---------
// One warp per token; lane l owns experts l and l+32. Reads precomputed
// logits from g_l.
#define EPI_THREADS 256   // 8 warps -> 8 tokens per block

__global__ __launch_bounds__(EPI_THREADS) void epilogue_kernel(
    float* __restrict__ out, int out_size)
{
    const int tid  = threadIdx.x;
    const int lane = tid & 31;
    const int warp = tid >> 5;
    const int b    = blockIdx.x * (EPI_THREADS / 32) + warp;

    const int  OFF_L = BTOK * NEXP;
    const int  OFF_W = 2 * BTOK * NEXP;
    const int  OFF_I = 3 * BTOK * NEXP;
    const bool wl = out_size >= OFF_W;
    const bool ww = out_size >= OFF_I;
    const bool wi = out_size >= OFF_I + 2 * BTOK;

    const size_t base = (size_t)b * NEXP;
    const float l0 = g_l[base + lane];
    const float l1 = g_l[base + lane + 32];

    // softmax over 64
    float m = fmaxf(l0, l1);
#pragma unroll
    for (int off = 16; off; off >>= 1)
        m = fmaxf(m, __shfl_xor_sync(0xffffffffu, m, off));
    const float e0 = expf(l0 - m);
    const float e1 = expf(l1 - m);
    float sden = e0 + e1;
#pragma unroll
    for (int off = 16; off; off >>= 1)
        sden += __shfl_xor_sync(0xffffffffu, sden, off);
    const float w0 = e0 / sden;
    const float w1 = e1 / sden;

    // top-1 (lower index wins ties -> matches jax.lax.top_k)
    float bv; int bi;
    if (w0 >= w1) { bv = w0; bi = lane; } else { bv = w1; bi = lane + 32; }
#pragma unroll
    for (int off = 16; off; off >>= 1) {
        float ov = __shfl_xor_sync(0xffffffffu, bv, off);
        int   oi = __shfl_xor_sync(0xffffffffu, bi, off);
        if (ov > bv || (ov == bv && oi < bi)) { bv = ov; bi = oi; }
    }
    // top-2 (exclude bi; weights >= 0 so -1 acts as -inf)
    float d0 = (lane == bi)      ? -1.f : w0;
    float d1 = (lane + 32 == bi) ? -1.f : w1;
    float bv2; int bi2;
    if (d0 >= d1) { bv2 = d0; bi2 = lane; } else { bv2 = d1; bi2 = lane + 32; }
#pragma unroll
    for (int off = 16; off; off >>= 1) {
        float ov = __shfl_xor_sync(0xffffffffu, bv2, off);
        int   oi = __shfl_xor_sync(0xffffffffu, bi2, off);
        if (ov > bv2 || (ov == bv2 && oi < bi2)) { bv2 = ov; bi2 = oi; }
    }

    const float denom = bv + bv2 + 1e-6f;
    const float r1 = bv / denom;
    const float r2 = bv2 / denom;

    const float cA = (lane == bi)      ? r1 : (lane == bi2)      ? r2 : 0.f;
    const float cB = (lane + 32 == bi) ? r1 : (lane + 32 == bi2) ? r2 : 0.f;
    out[base + lane]      = cA;
    out[base + lane + 32] = cB;
    if (wl) { out[OFF_L + base + lane] = l0; out[OFF_L + base + lane + 32] = l1; }
    if (ww) { out[OFF_W + base + lane] = w0; out[OFF_W + base + lane + 32] = w1; }
    if (wi && lane == 0) {
        out[OFF_I + (size_t)b * 2]     = (float)bi;
        out[OFF_I + (size_t)b * 2 + 1] = (float)bi2;
    }
}

// ---------------- launch ----------------------------------------------------
extern "C" void kernel_launch(void* const* d_in, const int* in_sizes, int n_in,
                              void* d_out, int out_size)
{
    const float* mm    = (const float*)d_in[0];
    const float* qf    = (const float*)d_in[1];
    const float* W_qe1 = (const float*)d_in[2];
    const float* b_qe1 = (const float*)d_in[3];
    const float* W_qe2 = (const float*)d_in[4];
    const float* b_qe2 = (const float*)d_in[5];
    const float* W_fus = (const float*)d_in[6];
    const float* b_fus = (const float*)d_in[7];
    const float* W_g1  = (const float*)d_in[8];
    const float* W_g2  = (const float*)d_in[9];
    float* out = (float*)d_out;

    float *p_q1, *p_q, *p_t, *p_l;
    cudaGetSymbolAddress((void**)&p_q1, g_q1);
    cudaGetSymbolAddress((void**)&p_q,  g_q);
    cudaGetSymbolAddress((void**)&p_t,  g_t);
    cudaGetSymbolAddress((void**)&p_l,  g_l);

    const dim3 blk(256);
    const int mblocks = BTOK / BM;   // 512

    // q1 = relu(qf @ W_qe1^T + b_qe1)
    gemm_bias_act<<<dim3(HID / BN, mblocks), blk>>>(
        qf, nullptr, DIN, DIN, W_qe1, b_qe1, p_q1, HID, 1);
    // q = q1 @ W_qe2^T + b_qe2
    gemm_bias_act<<<dim3(HID / BN, mblocks), blk>>>(
        p_q1, nullptr, HID, HID, W_qe2, b_qe2, p_q, HID, 0);
    // fused = relu([mm | q] @ W_fus^T + b_fus)   (reuses g_q1)
    gemm_bias_act<<<dim3(HID / BN, mblocks), blk>>>(
        mm, p_q, HID, 2 * HID, W_fus, b_fus, p_q1, HID, 1);
    // t = tanh(fused @ W_g1^T)
    gemm_bias_act<<<dim3(FOURE / BN, mblocks), blk>>>(
        p_q1, nullptr, HID, HID, W_g1, nullptr, p_t, FOURE, 2);
    // logits = t @ W_g2^T
    gemm_bias_act<<<dim3(NEXP / BN, mblocks), blk>>>(
        p_t, nullptr, FOURE, FOURE, W_g2, nullptr, p_l, NEXP, 0);

    // softmax + top2 + scatter (memory-bound)
    epilogue_kernel<<<BTOK / (EPI_THREADS / 32), EPI_THREADS>>>(out, out_size);
}

// round 10
// speedup vs baseline: 1.0234x; 1.0234x over previous
#include <cuda_runtime.h>
#include <cstdint>

// Problem constants
#define BTOK  65536
#define HID   512
#define DIN   512
#define NEXP  64
#define FOURE 256

// ---------------- scratch (static __device__, no allocation) ----------------
__device__ float g_q1[(size_t)BTOK * HID];   // qe1 output, reused for fused
__device__ float g_q [(size_t)BTOK * HID];   // qe2 output
__device__ float g_t [(size_t)BTOK * FOURE]; // tanh(fused @ Wg1^T)
__device__ float g_l [(size_t)BTOK * NEXP];  // logits

// ---------------- packed f32x2 helpers (sm_103a) ----------------------------
typedef unsigned long long u64;

__device__ __forceinline__ u64 fma2(u64 a, u64 b, u64 c) {
    u64 d;
    asm("fma.rn.f32x2 %0, %1, %2, %3;" : "=l"(d) : "l"(a), "l"(b), "l"(c));
    return d;
}
__device__ __forceinline__ u64 add2(u64 a, u64 b) {
    u64 d;
    asm("add.rn.f32x2 %0, %1, %2;" : "=l"(d) : "l"(a), "l"(b));
    return d;
}
__device__ __forceinline__ u64 dup2(float x) {
    u64 d;
    asm("mov.b64 %0, {%1, %1};" : "=l"(d) : "f"(x));
    return d;
}
__device__ __forceinline__ float2 unpk2(u64 a) {
    float2 r;
    asm("mov.b64 {%0, %1}, %2;" : "=f"(r.x), "=f"(r.y) : "l"(a));
    return r;
}

// ---------------- chunked-Kahan tiled fp32 GEMM: C = act(A @ W^T) -----------
// Register-fat tile: each thread computes 8 rows (4 packed pairs) x NCOL cols
// (cols tcol + 16*j). Per k-step LDS phases: a = 2x LDS.128 (~8), b = NCOL x
// LDS.32 conflict-free broadcast (~NCOL) -> LSU/FMA balanced at NCOL=8.
// Chunk structure (16-term ascending plain-FMA chunks per BKK=16 tile, packed
// Kahan fold) is bit-identical to the previous passing rounds.
// A is logically [M, K]; columns [0,K0) from A0 (row stride K0), columns
// [K0,K) from A1 (row stride K-K0).  W is [N, K] row-major.
#define BM 128
#define BKK 16

template <int NCOL>
__global__ void __launch_bounds__(256, NCOL == 8 ? 1 : 2) gemm_bias_act(
    const float* __restrict__ A0, const float* __restrict__ A1, int K0, int K,
    const float* __restrict__ W, const float* __restrict__ bias,
    float* __restrict__ C, int N, int act)
{
    constexpr int BN = 16 * NCOL;
    __shared__ __align__(16) float As[BKK][BM];
    __shared__ __align__(16) float Bs[BKK][BN];

    const int tid  = threadIdx.x;
    const int m0   = blockIdx.y * BM;
    const int n0   = blockIdx.x * BN;
    const int lr   = tid >> 2;          // 0..63
    const int lc   = (tid & 3) << 2;    // 0,4,8,12 (float4 col)
    const int trow = (tid >> 4) << 3;   // 0..120 step 8
    const int tcol = tid & 15;          // 0..15; cols tcol + 16*j

    const u64 MONE = 0xbf800000bf800000ULL;  // (-1.0f, -1.0f)

    // S[pi][j]: rows (trow+2pi, trow+2pi+1), col n0+tcol+16j.
    u64 S[4][NCOL], Cn[4][NCOL];
#pragma unroll
    for (int pi = 0; pi < 4; pi++)
#pragma unroll
        for (int j = 0; j < NCOL; j++) { S[pi][j] = 0ull; Cn[pi][j] = 0ull; }

    for (int kt = 0; kt < K; kt += BKK) {
        const int gk = kt + lc;
        float4 av0, av1;
        if (gk < K0) {
            av0 = *(const float4*)(A0 + (size_t)(m0 + lr)      * K0 + gk);
            av1 = *(const float4*)(A0 + (size_t)(m0 + lr + 64) * K0 + gk);
        } else {
            const int K1 = K - K0;
            av0 = *(const float4*)(A1 + (size_t)(m0 + lr)      * K1 + (gk - K0));
            av1 = *(const float4*)(A1 + (size_t)(m0 + lr + 64) * K1 + (gk - K0));
        }
        const float4 bv0 = *(const float4*)(W + (size_t)(n0 + lr) * K + gk);
        float4 bv1;
        if (BN == 128)
            bv1 = *(const float4*)(W + (size_t)(n0 + lr + 64) * K + gk);

        As[lc + 0][lr] = av0.x; As[lc + 1][lr] = av0.y;
        As[lc + 2][lr] = av0.z; As[lc + 3][lr] = av0.w;
        As[lc + 0][lr + 64] = av1.x; As[lc + 1][lr + 64] = av1.y;
        As[lc + 2][lr + 64] = av1.z; As[lc + 3][lr + 64] = av1.w;

        Bs[lc + 0][lr] = bv0.x; Bs[lc + 1][lr] = bv0.y;
        Bs[lc + 2][lr] = bv0.z; Bs[lc + 3][lr] = bv0.w;
        if (BN == 128) {
            Bs[lc + 0][lr + 64] = bv1.x; Bs[lc + 1][lr + 64] = bv1.y;
            Bs[lc + 2][lr + 64] = bv1.z; Bs[lc + 3][lr + 64] = bv1.w;
        }

        __syncthreads();

        // chunk accumulators (plain packed FMA, independent chains)
        u64 P[4][NCOL];
#pragma unroll
        for (int pi = 0; pi < 4; pi++)
#pragma unroll
            for (int j = 0; j < NCOL; j++) P[pi][j] = 0ull;

#pragma unroll
        for (int k = 0; k < BKK; k++) {
            const ulonglong2 aq0 = *(const ulonglong2*)&As[k][trow];      // LDS.128
            const ulonglong2 aq1 = *(const ulonglong2*)&As[k][trow + 4];  // LDS.128
            u64 ap[4] = { aq0.x, aq0.y, aq1.x, aq1.y };
            u64 bd[NCOL];
#pragma unroll
            for (int j = 0; j < NCOL; j++)
                bd[j] = dup2(Bs[k][tcol + 16 * j]);                       // LDS.32 cf
#pragma unroll
            for (int j = 0; j < NCOL; j++)
#pragma unroll
                for (int pi = 0; pi < 4; pi++)
                    P[pi][j] = fma2(ap[pi], bd[j], P[pi][j]);
        }

        // Kahan fold of chunk sums into (S, Cn)
#pragma unroll
        for (int pi = 0; pi < 4; pi++)
#pragma unroll
            for (int j = 0; j < NCOL; j++) {
                u64 y = add2(P[pi][j], Cn[pi][j]);
                u64 t = add2(S[pi][j], y);
                u64 u = fma2(t, MONE, S[pi][j]);   // s - t (exact)
                Cn[pi][j] = add2(y, u);            // y - (t - s)
                S[pi][j]  = t;
            }

        __syncthreads();
    }

    float bb[NCOL];
#pragma unroll
    for (int j = 0; j < NCOL; j++) bb[j] = bias ? bias[n0 + tcol + 16 * j] : 0.f;

#pragma unroll
    for (int pi = 0; pi < 4; pi++) {
        float* cp0 = C + (size_t)(m0 + trow + 2 * pi)     * N + n0 + tcol;
        float* cp1 = C + (size_t)(m0 + trow + 2 * pi + 1) * N + n0 + tcol;
#pragma unroll
        for (int j = 0; j < NCOL; j++) {
            float2 v = unpk2(S[pi][j]);
            float xl = v.x + bb[j];
            float xh = v.y + bb[j];
            if (act == 1)      { xl = fmaxf(xl, 0.f); xh = fmaxf(xh, 0.f); }
            else if (act == 2) { xl = tanhf(xl);      xh = tanhf(xh); }
            cp0[16 * j] = xl;
            cp1[16 * j] = xh;
        }
    }
}

// ---------------- epilogue: softmax + top2 + scatter (memory-bound) ---------
// One warp per token; lane l owns experts l and l+32. Reads precomputed
// logits from g_l.
#define EPI_THREADS 256   // 8 warps -> 8 tokens per block

__global__ __launch_bounds__(EPI_THREADS) void epilogue_kernel(
    float* __restrict__ out, int out_size)
{
    const int tid  = threadIdx.x;
    const int lane = tid & 31;
    const int warp = tid >> 5;
    const int b    = blockIdx.x * (EPI_THREADS / 32) + warp;

    const int  OFF_L = BTOK * NEXP;
    const int  OFF_W = 2 * BTOK * NEXP;
    const int  OFF_I = 3 * BTOK * NEXP;
    const bool wl = out_size >= OFF_W;
    const bool ww = out_size >= OFF_I;
    const bool wi = out_size >= OFF_I + 2 * BTOK;

    const size_t base = (size_t)b * NEXP;
    const float l0 = g_l[base + lane];
    const float l1 = g_l[base + lane + 32];

    // softmax over 64
    float m = fmaxf(l0, l1);
#pragma unroll
    for (int off = 16; off; off >>= 1)
        m = fmaxf(m, __shfl_xor_sync(0xffffffffu, m, off));
    const float e0 = expf(l0 - m);
    const float e1 = expf(l1 - m);
    float sden = e0 + e1;
#pragma unroll
    for (int off = 16; off; off >>= 1)
        sden += __shfl_xor_sync(0xffffffffu, sden, off);
    const float w0 = e0 / sden;
    const float w1 = e1 / sden;

    // top-1 (lower index wins ties -> matches jax.lax.top_k)
    float bv; int bi;
    if (w0 >= w1) { bv = w0; bi = lane; } else { bv = w1; bi = lane + 32; }
#pragma unroll
    for (int off = 16; off; off >>= 1) {
        float ov = __shfl_xor_sync(0xffffffffu, bv, off);
        int   oi = __shfl_xor_sync(0xffffffffu, bi, off);
        if (ov > bv || (ov == bv && oi < bi)) { bv = ov; bi = oi; }
    }
    // top-2 (exclude bi; weights >= 0 so -1 acts as -inf)
    float d0 = (lane == bi)      ? -1.f : w0;
    float d1 = (lane + 32 == bi) ? -1.f : w1;
    float bv2; int bi2;
    if (d0 >= d1) { bv2 = d0; bi2 = lane; } else { bv2 = d1; bi2 = lane + 32; }
#pragma unroll
    for (int off = 16; off; off >>= 1) {
        float ov = __shfl_xor_sync(0xffffffffu, bv2, off);
        int   oi = __shfl_xor_sync(0xffffffffu, bi2, off);
        if (ov > bv2 || (ov == bv2 && oi < bi2)) { bv2 = ov; bi2 = oi; }
    }

    const float denom = bv + bv2 + 1e-6f;
    const float r1 = bv / denom;
    const float r2 = bv2 / denom;

    const float cA = (lane == bi)      ? r1 : (lane == bi2)      ? r2 : 0.f;
    const float cB = (lane + 32 == bi) ? r1 : (lane + 32 == bi2) ? r2 : 0.f;
    out[base + lane]      = cA;
    out[base + lane + 32] = cB;
    if (wl) { out[OFF_L + base + lane] = l0; out[OFF_L + base + lane + 32] = l1; }
    if (ww) { out[OFF_W + base + lane] = w0; out[OFF_W + base + lane + 32] = w1; }
    if (wi && lane == 0) {
        out[OFF_I + (size_t)b * 2]     = (float)bi;
        out[OFF_I + (size_t)b * 2 + 1] = (float)bi2;
    }
}

// ---------------- launch ----------------------------------------------------
extern "C" void kernel_launch(void* const* d_in, const int* in_sizes, int n_in,
                              void* d_out, int out_size)
{
    const float* mm    = (const float*)d_in[0];
    const float* qf    = (const float*)d_in[1];
    const float* W_qe1 = (const float*)d_in[2];
    const float* b_qe1 = (const float*)d_in[3];
    const float* W_qe2 = (const float*)d_in[4];
    const float* b_qe2 = (const float*)d_in[5];
    const float* W_fus = (const float*)d_in[6];
    const float* b_fus = (const float*)d_in[7];
    const float* W_g1  = (const float*)d_in[8];
    const float* W_g2  = (const float*)d_in[9];
    float* out = (float*)d_out;

    float *p_q1, *p_q, *p_t, *p_l;
    cudaGetSymbolAddress((void**)&p_q1, g_q1);
    cudaGetSymbolAddress((void**)&p_q,  g_q);
    cudaGetSymbolAddress((void**)&p_t,  g_t);
    cudaGetSymbolAddress((void**)&p_l,  g_l);

    const dim3 blk(256);
    const int mblocks = BTOK / BM;   // 512

    // q1 = relu(qf @ W_qe1^T + b_qe1)          N=512 -> BN=128
    gemm_bias_act<8><<<dim3(HID / 128, mblocks), blk>>>(
        qf, nullptr, DIN, DIN, W_qe1, b_qe1, p_q1, HID, 1);
    // q = q1 @ W_qe2^T + b_qe2                 N=512
    gemm_bias_act<8><<<dim3(HID / 128, mblocks), blk>>>(
        p_q1, nullptr, HID, HID, W_qe2, b_qe2, p_q, HID, 0);
    // fused = relu([mm | q] @ W_fus^T + b_fus) N=512 (reuses g_q1)
    gemm_bias_act<8><<<dim3(HID / 128, mblocks), blk>>>(
        mm, p_q, HID, 2 * HID, W_fus, b_fus, p_q1, HID, 1);
    // t = tanh(fused @ W_g1^T)                 N=256
    gemm_bias_act<8><<<dim3(FOURE / 128, mblocks), blk>>>(
        p_q1, nullptr, HID, HID, W_g1, nullptr, p_t, FOURE, 2);
    // logits = t @ W_g2^T                      N=64 -> BN=64 variant
    gemm_bias_act<4><<<dim3(NEXP / 64, mblocks), blk>>>(
        p_t, nullptr, FOURE, FOURE, W_g2, nullptr, p_l, NEXP, 0);

    // softmax + top2 + scatter (memory-bound)
    epilogue_kernel<<<BTOK / (EPI_THREADS / 32), EPI_THREADS>>>(out, out_size);
}

// round 11
// speedup vs baseline: 1.1173x; 1.0917x over previous
#include <cuda_runtime.h>
#include <cstdint>

// Problem constants
#define BTOK  65536
#define HID   512
#define DIN   512
#define NEXP  64
#define FOURE 256

// ---------------- scratch (static __device__, no allocation) ----------------
__device__ float g_q1[(size_t)BTOK * HID];   // qe1 output, reused for fused
__device__ float g_q [(size_t)BTOK * HID];   // qe2 output
__device__ float g_t [(size_t)BTOK * FOURE]; // tanh(fused @ Wg1^T)
__device__ float g_l [(size_t)BTOK * NEXP];  // logits

// ---------------- packed f32x2 helpers (sm_103a) ----------------------------
typedef unsigned long long u64;

__device__ __forceinline__ u64 fma2(u64 a, u64 b, u64 c) {
    u64 d;
    asm("fma.rn.f32x2 %0, %1, %2, %3;" : "=l"(d) : "l"(a), "l"(b), "l"(c));
    return d;
}
__device__ __forceinline__ u64 add2(u64 a, u64 b) {
    u64 d;
    asm("add.rn.f32x2 %0, %1, %2;" : "=l"(d) : "l"(a), "l"(b));
    return d;
}
__device__ __forceinline__ u64 dup2(float x) {
    u64 d;
    asm("mov.b64 %0, {%1, %1};" : "=l"(d) : "f"(x));
    return d;
}
__device__ __forceinline__ float2 unpk2(u64 a) {
    float2 r;
    asm("mov.b64 {%0, %1}, %2;" : "=f"(r.x), "=f"(r.y) : "l"(a));
    return r;
}

// ---------------- chunked-Kahan double-buffered fp32 GEMM -------------------
// 128-thread blocks, BM=64, BN=16*NCOL. Thread tile: 8 rows (4 packed pairs)
// x NCOL cols (tcol + 16j). Double-buffered smem + register prefetch: LDG
// tile t+1 issued before computing tile t; one __syncthreads per tile; two
// independent blocks per SM overlap bar/compute.
// Chunk numerics (16-term ascending plain-FMA chunks, packed Kahan fold with
// Cn = -compensation) bit-identical to the previous passing rounds.
// A is logically [M, K]; columns [0,K0) from A0 (row stride K0), columns
// [K0,K) from A1 (row stride K-K0).  W is [N, K] row-major.

#define LDG_TILE(kt)                                                          \
    {                                                                         \
        _Pragma("unroll")                                                     \
        for (int c = 0; c < 2; c++) {                                         \
            const int fidx = 2 * tid + c;                                     \
            const int ar = fidx >> 2;                                         \
            const int ac = (fidx & 3) << 2;                                   \
            const int gk = (kt) + ac;                                         \
            rA[c] = (gk < K0)                                                 \
                ? *(const float4*)(A0 + (size_t)(m0 + ar) * K0 + gk)          \
                : *(const float4*)(A1 + (size_t)(m0 + ar) * (K - K0) + (gk - K0)); \
        }                                                                     \
        _Pragma("unroll")                                                     \
        for (int c = 0; c < CB; c++) {                                        \
            const int fidx = CB * tid + c;                                    \
            const int br = fidx >> 2;                                         \
            const int bc = (fidx & 3) << 2;                                   \
            rB[c] = *(const float4*)(W + (size_t)(n0 + br) * K + (kt) + bc);  \
        }                                                                     \
    }

#define STS_TILE(buf)                                                         \
    {                                                                         \
        _Pragma("unroll")                                                     \
        for (int c = 0; c < 2; c++) {                                         \
            const int fidx = 2 * tid + c;                                     \
            const int ar = fidx >> 2;                                         \
            const int ac = (fidx & 3) << 2;                                   \
            As[buf][ac + 0][ar] = rA[c].x;                                    \
            As[buf][ac + 1][ar] = rA[c].y;                                    \
            As[buf][ac + 2][ar] = rA[c].z;                                    \
            As[buf][ac + 3][ar] = rA[c].w;                                    \
        }                                                                     \
        _Pragma("unroll")                                                     \
        for (int c = 0; c < CB; c++) {                                        \
            const int fidx = CB * tid + c;                                    \
            const int br = fidx >> 2;                                         \
            const int bc = (fidx & 3) << 2;                                   \
            Bs[buf][bc + 0][br] = rB[c].x;                                    \
            Bs[buf][bc + 1][br] = rB[c].y;                                    \
            Bs[buf][bc + 2][br] = rB[c].z;                                    \
            Bs[buf][bc + 3][br] = rB[c].w;                                    \
        }                                                                     \
    }

template <int NCOL>
__global__ void __launch_bounds__(128, 2) gemm_db(
    const float* __restrict__ A0, const float* __restrict__ A1, int K0, int K,
    const float* __restrict__ W, const float* __restrict__ bias,
    float* __restrict__ C, int N, int act)
{
    constexpr int BN = 16 * NCOL;
    constexpr int CB = BN / 32;           // B float4 loads per thread
    __shared__ __align__(16) float As[2][16][64];
    __shared__ __align__(16) float Bs[2][16][BN];

    const int tid  = threadIdx.x;
    const int m0   = blockIdx.y * 64;
    const int n0   = blockIdx.x * BN;
    const int trow = (tid >> 4) << 3;     // 0..56 step 8
    const int tcol = tid & 15;            // 0..15; cols tcol + 16*j

    const u64 MONE = 0xbf800000bf800000ULL;  // (-1.0f, -1.0f)

    u64 S[4][NCOL], Cn[4][NCOL];
#pragma unroll
    for (int pi = 0; pi < 4; pi++)
#pragma unroll
        for (int j = 0; j < NCOL; j++) { S[pi][j] = 0ull; Cn[pi][j] = 0ull; }

    float4 rA[2], rB[CB];

    LDG_TILE(0);
    STS_TILE(0);
    __syncthreads();

    int p = 0;
    for (int kt = 0; kt < K; kt += 16) {
        const bool nxt = (kt + 16) < K;
        if (nxt) LDG_TILE(kt + 16);

        // 16-term chunk: plain packed FMA into P (independent chains)
        u64 P[4][NCOL];
#pragma unroll
        for (int pi = 0; pi < 4; pi++)
#pragma unroll
            for (int j = 0; j < NCOL; j++) P[pi][j] = 0ull;

#pragma unroll
        for (int k = 0; k < 16; k++) {
            u64 ap[4];
#pragma unroll
            for (int pi = 0; pi < 4; pi++)
                ap[pi] = *(const u64*)&As[p][k][trow + 2 * pi];  // LDS.64 bcast
#pragma unroll
            for (int j = 0; j < NCOL; j++) {
                const u64 bd = dup2(Bs[p][k][tcol + 16 * j]);    // LDS.32 cf
#pragma unroll
                for (int pi = 0; pi < 4; pi++)
                    P[pi][j] = fma2(ap[pi], bd, P[pi][j]);
            }
        }

        // Kahan fold of chunk sums into (S, Cn)
#pragma unroll
        for (int pi = 0; pi < 4; pi++)
#pragma unroll
            for (int j = 0; j < NCOL; j++) {
                u64 y = add2(P[pi][j], Cn[pi][j]);
                u64 t = add2(S[pi][j], y);
                u64 u = fma2(t, MONE, S[pi][j]);   // s - t (exact)
                Cn[pi][j] = add2(y, u);            // y - (t - s)
                S[pi][j]  = t;
            }

        if (nxt) {
            STS_TILE(p ^ 1);
            __syncthreads();
        }
        p ^= 1;
    }

    float bb[NCOL];
#pragma unroll
    for (int j = 0; j < NCOL; j++) bb[j] = bias ? bias[n0 + tcol + 16 * j] : 0.f;

#pragma unroll
    for (int pi = 0; pi < 4; pi++) {
        float* cp0 = C + (size_t)(m0 + trow + 2 * pi)     * N + n0 + tcol;
        float* cp1 = C + (size_t)(m0 + trow + 2 * pi + 1) * N + n0 + tcol;
#pragma unroll
        for (int j = 0; j < NCOL; j++) {
            float2 v = unpk2(S[pi][j]);
            float xl = v.x + bb[j];
            float xh = v.y + bb[j];
            if (act == 1)      { xl = fmaxf(xl, 0.f); xh = fmaxf(xh, 0.f); }
            else if (act == 2) { xl = tanhf(xl);      xh = tanhf(xh); }
            cp0[16 * j] = xl;
            cp1[16 * j] = xh;
        }
    }
}

// ---------------- epilogue: softmax + top2 + scatter (memory-bound) ---------
#define EPI_THREADS 256   // 8 warps -> 8 tokens per block

__global__ __launch_bounds__(EPI_THREADS) void epilogue_kernel(
    float* __restrict__ out, int out_size)
{
    const int tid  = threadIdx.x;
    const int lane = tid & 31;
    const int warp = tid >> 5;
    const int b    = blockIdx.x * (EPI_THREADS / 32) + warp;

    const int  OFF_L = BTOK * NEXP;
    const int  OFF_W = 2 * BTOK * NEXP;
    const int  OFF_I = 3 * BTOK * NEXP;
    const bool wl = out_size >= OFF_W;
    const bool ww = out_size >= OFF_I;
    const bool wi = out_size >= OFF_I + 2 * BTOK;

    const size_t base = (size_t)b * NEXP;
    const float l0 = g_l[base + lane];
    const float l1 = g_l[base + lane + 32];

    // softmax over 64
    float m = fmaxf(l0, l1);
#pragma unroll
    for (int off = 16; off; off >>= 1)
        m = fmaxf(m, __shfl_xor_sync(0xffffffffu, m, off));
    const float e0 = expf(l0 - m);
    const float e1 = expf(l1 - m);
    float sden = e0 + e1;
#pragma unroll
    for (int off = 16; off; off >>= 1)
        sden += __shfl_xor_sync(0xffffffffu, sden, off);
    const float w0 = e0 / sden;
    const float w1 = e1 / sden;

    // top-1 (lower index wins ties -> matches jax.lax.top_k)
    float bv; int bi;
    if (w0 >= w1) { bv = w0; bi = lane; } else { bv = w1; bi = lane + 32; }
#pragma unroll
    for (int off = 16; off; off >>= 1) {
        float ov = __shfl_xor_sync(0xffffffffu, bv, off);
        int   oi = __shfl_xor_sync(0xffffffffu, bi, off);
        if (ov > bv || (ov == bv && oi < bi)) { bv = ov; bi = oi; }
    }
    // top-2 (exclude bi; weights >= 0 so -1 acts as -inf)
    float d0 = (lane == bi)      ? -1.f : w0;
    float d1 = (lane + 32 == bi) ? -1.f : w1;
    float bv2; int bi2;
    if (d0 >= d1) { bv2 = d0; bi2 = lane; } else { bv2 = d1; bi2 = lane + 32; }
#pragma unroll
    for (int off = 16; off; off >>= 1) {
        float ov = __shfl_xor_sync(0xffffffffu, bv2, off);
        int   oi = __shfl_xor_sync(0xffffffffu, bi2, off);
        if (ov > bv2 || (ov == bv2 && oi < bi2)) { bv2 = ov; bi2 = oi; }
    }

    const float denom = bv + bv2 + 1e-6f;
    const float r1 = bv / denom;
    const float r2 = bv2 / denom;

    const float cA = (lane == bi)      ? r1 : (lane == bi2)      ? r2 : 0.f;
    const float cB = (lane + 32 == bi) ? r1 : (lane + 32 == bi2) ? r2 : 0.f;
    out[base + lane]      = cA;
    out[base + lane + 32] = cB;
    if (wl) { out[OFF_L + base + lane] = l0; out[OFF_L + base + lane + 32] = l1; }
    if (ww) { out[OFF_W + base + lane] = w0; out[OFF_W + base + lane + 32] = w1; }
    if (wi && lane == 0) {
        out[OFF_I + (size_t)b * 2]     = (float)bi;
        out[OFF_I + (size_t)b * 2 + 1] = (float)bi2;
    }
}

// ---------------- launch ----------------------------------------------------
extern "C" void kernel_launch(void* const* d_in, const int* in_sizes, int n_in,
                              void* d_out, int out_size)
{
    const float* mm    = (const float*)d_in[0];
    const float* qf    = (const float*)d_in[1];
    const float* W_qe1 = (const float*)d_in[2];
    const float* b_qe1 = (const float*)d_in[3];
    const float* W_qe2 = (const float*)d_in[4];
    const float* b_qe2 = (const float*)d_in[5];
    const float* W_fus = (const float*)d_in[6];
    const float* b_fus = (const float*)d_in[7];
    const float* W_g1  = (const float*)d_in[8];
    const float* W_g2  = (const float*)d_in[9];
    float* out = (float*)d_out;

    float *p_q1, *p_q, *p_t, *p_l;
    cudaGetSymbolAddress((void**)&p_q1, g_q1);
    cudaGetSymbolAddress((void**)&p_q,  g_q);
    cudaGetSymbolAddress((void**)&p_t,  g_t);
    cudaGetSymbolAddress((void**)&p_l,  g_l);

    const dim3 blk(128);
    const int mblocks = BTOK / 64;   // 1024

    // q1 = relu(qf @ W_qe1^T + b_qe1)          N=512 -> BN=128
    gemm_db<8><<<dim3(HID / 128, mblocks), blk>>>(
        qf, nullptr, DIN, DIN, W_qe1, b_qe1, p_q1, HID, 1);
    // q = q1 @ W_qe2^T + b_qe2                 N=512
    gemm_db<8><<<dim3(HID / 128, mblocks), blk>>>(
        p_q1, nullptr, HID, HID, W_qe2, b_qe2, p_q, HID, 0);
    // fused = relu([mm | q] @ W_fus^T + b_fus) N=512, K=1024 (reuses g_q1)
    gemm_db<8><<<dim3(HID / 128, mblocks), blk>>>(
        mm, p_q, HID, 2 * HID, W_fus, b_fus, p_q1, HID, 1);
    // t = tanh(fused @ W_g1^T)                 N=256
    gemm_db<8><<<dim3(FOURE / 128, mblocks), blk>>>(
        p_q1, nullptr, HID, HID, W_g1, nullptr, p_t, FOURE, 2);
    // logits = t @ W_g2^T                      N=64 -> BN=64 variant
    gemm_db<4><<<dim3(NEXP / 64, mblocks), blk>>>(
        p_t, nullptr, FOURE, FOURE, W_g2, nullptr, p_l, NEXP, 0);

    // softmax + top2 + scatter (memory-bound)
    epilogue_kernel<<<BTOK / (EPI_THREADS / 32), EPI_THREADS>>>(out, out_size);
}